// round 17
// baseline (speedup 1.0000x reference)
#include <cuda_runtime.h>
#include <cuda_bf16.h>
#include <cstdint>

#define B_DIM 16
#define M_DIM 2048
#define F_IN  128
#define F_OUT 64
#define ALPHA 0.2f

// ---------------------------------------------------------------------------
// __device__ scratch (allocation-free rule)
// ---------------------------------------------------------------------------
__device__ float g_r  [(size_t)B_DIM * M_DIM];
__device__ float g_E2 [(size_t)B_DIM * M_DIM];
__device__ float g_E2a[(size_t)B_DIM * M_DIM];
// Wh transposed + bf16 2-term split: [B][F_OUT][M]  (hi + lo)
__device__ __nv_bfloat16 g_WhT_h[(size_t)B_DIM * F_OUT * M_DIM];
__device__ __nv_bfloat16 g_WhT_l[(size_t)B_DIM * F_OUT * M_DIM];

// ---------------------------------------------------------------------------
// helpers
// ---------------------------------------------------------------------------
__device__ __forceinline__ uint32_t smem_u32(const void* p) {
    uint32_t a;
    asm("{ .reg .u64 t; cvta.to.shared.u64 t, %1; cvt.u32.u64 %0, t; }"
        : "=r"(a) : "l"(p));
    return a;
}
__device__ __forceinline__ uint32_t pack_bf16(float a, float b) {
    uint32_t r;
    asm("cvt.rn.satfinite.bf16x2.f32 %0, %1, %2;" : "=r"(r) : "f"(b), "f"(a));
    return r;
}
__device__ __forceinline__ void ldsm4(uint32_t* r, uint32_t addr) {
    asm volatile("ldmatrix.sync.aligned.m8n8.x4.shared.b16 {%0,%1,%2,%3}, [%4];"
                 : "=r"(r[0]), "=r"(r[1]), "=r"(r[2]), "=r"(r[3]) : "r"(addr));
}
__device__ __forceinline__ void mma_bf16(float* d, const uint32_t* a,
                                         uint32_t b0, uint32_t b1) {
    asm volatile(
        "mma.sync.aligned.m16n8k16.row.col.f32.bf16.bf16.f32 "
        "{%0,%1,%2,%3}, {%4,%5,%6,%7}, {%8,%9}, {%0,%1,%2,%3};"
        : "+f"(d[0]), "+f"(d[1]), "+f"(d[2]), "+f"(d[3])
        : "r"(a[0]), "r"(a[1]), "r"(a[2]), "r"(a[3]), "r"(b0), "r"(b1));
}
__device__ __forceinline__ void cpa16(uint32_t dst, const void* src) {
    asm volatile("cp.async.cg.shared.global [%0], [%1], 16;"
                 :: "r"(dst), "l"(src) : "memory");
}
__device__ __forceinline__ void lds128f(float4& v, uint32_t addr) {
    asm volatile("ld.shared.v4.f32 {%0,%1,%2,%3}, [%4];"
                 : "=f"(v.x), "=f"(v.y), "=f"(v.z), "=f"(v.w) : "r"(addr));
}
#define CP_COMMIT() asm volatile("cp.async.commit_group;" ::: "memory")
#define CP_WAIT2()  asm volatile("cp.async.wait_group 2;" ::: "memory")
#define CP_WAIT0()  asm volatile("cp.async.wait_group 0;" ::: "memory")
// named barriers (producer/consumer handshake), count = all 512 threads
#define BAR_SYNC(id)   asm volatile("bar.sync %0, 512;"   :: "r"(id) : "memory")
#define BAR_ARRIVE(id) asm volatile("bar.arrive %0, 512;" :: "r"(id) : "memory")
#define FULL(s)  (1 + (s))
#define EMPTY(s) (3 + (s))

// ---------------------------------------------------------------------------
// Kernel 1: Wh = h @ W ; f1/f2 dots ; separable-exp precomputes ;
// Wh transposed + rn bf16 split. 64 rows / 512-thr CTA. (unchanged)
// ---------------------------------------------------------------------------
#define WH_WS   0
#define WH_HS   32768
#define WH_WHS  65536
#define WH_SMEM 82944

__global__ __launch_bounds__(512) void k_wh(const float* __restrict__ h,
                                            const float* __restrict__ W,
                                            const float* __restrict__ a) {
    extern __shared__ char wsm[];
    float* Ws  = (float*)(wsm + WH_WS);
    float* hs  = (float*)(wsm + WH_HS);
    float* whs = (float*)(wsm + WH_WHS);
    const int tid = threadIdx.x;
    const size_t row0 = (size_t)blockIdx.x * 64;
    const int b_    = (int)(row0 >> 11);
    const int jbase = (int)(row0 & 2047);

    {
        const float4* ws = (const float4*)W;
        float4* wd = (float4*)Ws;
#pragma unroll
        for (int k = 0; k < 4; ++k) wd[tid + 512 * k] = ws[tid + 512 * k];
        const float4* hsrc = (const float4*)(h + row0 * F_IN);
        float4* hdst = (float4*)hs;
#pragma unroll
        for (int k = 0; k < 4; ++k) hdst[tid + 512 * k] = hsrc[tid + 512 * k];
    }
    __syncthreads();

    const int c  = tid & 63;
    const int r0 = tid >> 6;
    float acc[8];
#pragma unroll
    for (int u = 0; u < 8; ++u) acc[u] = 0.f;
#pragma unroll 4
    for (int k = 0; k < F_IN; ++k) {
        const float wv = Ws[k * F_OUT + c];
#pragma unroll
        for (int u = 0; u < 8; ++u)
            acc[u] += hs[(r0 + 8 * u) * F_IN + k] * wv;
    }
#pragma unroll
    for (int u = 0; u < 8; ++u)
        whs[(r0 + 8 * u) * 68 + c] = acc[u];
    __syncthreads();

    {
        const int cc = tid >> 3;
        const int rq = tid & 7;
        float x[8];
#pragma unroll
        for (int u = 0; u < 8; ++u) x[u] = whs[(rq * 8 + u) * 68 + cc];
        uint32_t hh[4], ll[4];
#pragma unroll
        for (int q = 0; q < 4; ++q) {
            hh[q] = pack_bf16(x[2 * q], x[2 * q + 1]);
            const float l0 = x[2 * q]     - __uint_as_float(hh[q] << 16);
            const float l1 = x[2 * q + 1] - __uint_as_float(hh[q] & 0xFFFF0000u);
            ll[q] = pack_bf16(l0, l1);
        }
        const size_t idx = ((size_t)b_ * F_OUT + cc) * M_DIM + jbase + rq * 8;
        *(uint4*)(g_WhT_h + idx) = make_uint4(hh[0], hh[1], hh[2], hh[3]);
        *(uint4*)(g_WhT_l + idx) = make_uint4(ll[0], ll[1], ll[2], ll[3]);
    }

    if (tid < 128) {
        const int row   = tid >> 1;
        const int which = tid & 1;
        float f = 0.f;
#pragma unroll 8
        for (int k = 0; k < F_OUT; ++k)
            f += whs[row * 68 + k] * a[which * F_OUT + k];
        const size_t grow = row0 + row;
        if (which == 0) {
            g_r[grow] = expf((ALPHA - 1.0f) * f);
        } else {
            g_E2[grow]  = expf(f);
            g_E2a[grow] = expf(ALPHA * f);
        }
    }
}

// ---------------------------------------------------------------------------
// Kernel 2: WARP-SPECIALIZED fused masked-softmax + attn@Wh + elu.
// Grid (16,16): CTA = 128 rows x batch, 512 threads.
// Warps 0-7 PRODUCERS (software-pipelined: adj prefetched 1 tile ahead in
//   registers; e2/e2a ride in the B cp.async group and are read via LDS),
// Warps 8-15 CONSUMERS: LDSM + HMMA (4m x 2n, warp tile m32 x n32).
// B triple-buffered; staged on odd tiles AFTER the EMPTY sync that proves
// the target buffer free. One commit group per producer tile; CP_WAIT2 at
// tile t completes all groups <= t-2.
// ---------------------------------------------------------------------------
#define BI 128
#define NT 64
#define APITCH 80                // A row: 32 bf16 = 64B + 16 pad
#define BPITCH 144               // B row: 64 bf16 = 128B + 16 pad
#define A_BUF 20480              // hi 10240 + lo 10240
#define A_HL 10240
#define SB   40960               // 3 x 18944  (hi 9216 | lo 9216 | e2 256 | e2a 256)
#define B_BUF 18944
#define B_HL 9216
#define B_E2 18432               // e2 offset within buffer
#define SRS  97792               // 128 f32 r values
#define SLS  98304               // 128 f32 row sums
#define SMEM_TOTAL 98816

__global__ __launch_bounds__(512, 2) void k_gat(const int* __restrict__ adj,
                                                float* __restrict__ out) {
    extern __shared__ char smem[];
    const uint32_t sbase = smem_u32(smem);
    float* rsm = (float*)(smem + SRS);
    float* ls  = (float*)(smem + SLS);

    const int tid  = threadIdx.x;
    const int lane = tid & 31;
    const int w    = tid >> 5;           // warp 0..15
    const int b    = blockIdx.y;
    const int i0   = blockIdx.x * BI;
    const size_t brow = (size_t)b * M_DIM;
    const int P = (2 * blockIdx.x + blockIdx.y) & 31;   // stagger (j pairs)

    if (tid < 128) rsm[tid] = g_r[brow + i0 + tid];

#define STAGE_B(S) do {                                                       \
        const int jp0_ = (((S) + P) & 31) * 64;                               \
        const int bsr_ = tid >> 2;                                            \
        const int bc0_ = tid & 3;                                             \
        const size_t gsrc_ = ((size_t)b * F_OUT + bsr_) * M_DIM + jp0_;       \
        const uint32_t d0_ = sbase + SB + ((S) % 3) * B_BUF + bsr_ * BPITCH;  \
        cpa16(d0_ + bc0_ * 16,              g_WhT_h + gsrc_ + bc0_ * 8);      \
        cpa16(d0_ + (bc0_ + 4) * 16,        g_WhT_h + gsrc_ + (bc0_ + 4) * 8);\
        cpa16(d0_ + B_HL + bc0_ * 16,       g_WhT_l + gsrc_ + bc0_ * 8);      \
        cpa16(d0_ + B_HL + (bc0_ + 4) * 16, g_WhT_l + gsrc_ + (bc0_ + 4) * 8);\
        if (tid < 32) {                                                       \
            const int half_ = tid >> 4, q_ = tid & 15;                        \
            const float* s_ = (half_ ? g_E2a : g_E2) + brow + jp0_ + q_ * 4;  \
            cpa16(sbase + SB + ((S) % 3) * B_BUF + B_E2 + half_ * 256         \
                  + q_ * 16, s_);                                             \
        }                                                                     \
    } while (0)

    // ---- prologue: producers stage B(0), B(1); full drain so e2 is
    //      cross-thread visible after the __syncthreads ----
    if (w < 8) {
        STAGE_B(0);
        CP_COMMIT();
        STAGE_B(1);
        CP_COMMIT();
        CP_WAIT0();
    }
    __syncthreads();       // rsm + e2(0),e2(1) + B(0),B(1) visible

    if (w < 8) {
        // ================= PRODUCER =================
        const int pw   = w;
        const int jq   = lane & 7;       // int4 column group
        const int rsub = lane >> 3;      // 0..3
        float psum[4];
#pragma unroll
        for (int p = 0; p < 4; ++p) psum[p] = 0.f;

        // prefetch adj for tile 0
        int4 avc[4];
        {
            const int j0 = (2 * P & 63) * 32;
#pragma unroll
            for (int ps = 0; ps < 4; ++ps) {
                const int row = pw * 16 + ps * 4 + rsub;
                avc[ps] = *(const int4*)(adj + (brow + i0 + row) * (size_t)M_DIM
                                             + j0 + jq * 4);
            }
        }

#pragma unroll 1
        for (int t = 0; t < NT; ++t) {
            const int slot = t & 1;
            const int s = t >> 1;

            // A-slot free?  (also proves consumers finished tile t-2, so on
            // odd tiles buffer (s+2)%3 == (s-1)%3 is free for B staging)
            if (t >= 2) BAR_SYNC(EMPTY(slot));

            if ((t & 1) == 1 && (s + 2) < 32) STAGE_B(s + 2);
            CP_COMMIT();      // exactly one group per tile (may be empty)
            CP_WAIT2();       // all groups <= t-2 complete -> current B/e2 ready

            // prefetch adj for tile t+1 (latency hidden under p-compute)
            int4 avn[4];
            if (t + 1 < NT) {
                const int j0n = ((t + 1 + 2 * P) & 63) * 32;
#pragma unroll
                for (int ps = 0; ps < 4; ++ps) {
                    const int row = pw * 16 + ps * 4 + rsub;
                    avn[ps] = *(const int4*)(adj
                        + (brow + i0 + row) * (size_t)M_DIM + j0n + jq * 4);
                }
            }

            // e2/e2a for tile t from smem (staged with B pair s)
            float4 e2v, e2av;
            {
                const uint32_t eb = sbase + SB + (s % 3) * B_BUF + B_E2
                                  + (t & 1) * 128 + jq * 16;
                lds128f(e2v, eb);
                lds128f(e2av, eb + 256);
            }

            const uint32_t abase = sbase + slot * A_BUF;
#pragma unroll
            for (int ps = 0; ps < 4; ++ps) {
                const int row = pw * 16 + ps * 4 + rsub;
                const float rv = rsm[row];
                const int4 a = avc[ps];
                float p0 = fmaxf(e2v.x, rv * e2av.x) * __int_as_float(a.x * 0x3F800000);
                float p1 = fmaxf(e2v.y, rv * e2av.y) * __int_as_float(a.y * 0x3F800000);
                float p2 = fmaxf(e2v.z, rv * e2av.z) * __int_as_float(a.z * 0x3F800000);
                float p3 = fmaxf(e2v.w, rv * e2av.w) * __int_as_float(a.w * 0x3F800000);
                psum[ps] += (p0 + p1) + (p2 + p3);
                const uint32_t h01 = pack_bf16(p0, p1);
                const uint32_t h23 = pack_bf16(p2, p3);
                const uint32_t l01 = pack_bf16(p0 - __uint_as_float(h01 << 16),
                                               p1 - __uint_as_float(h01 & 0xFFFF0000u));
                const uint32_t l23 = pack_bf16(p2 - __uint_as_float(h23 << 16),
                                               p3 - __uint_as_float(h23 & 0xFFFF0000u));
                const uint32_t off = abase + row * APITCH + jq * 8;
                asm volatile("st.shared.v2.b32 [%0], {%1, %2};"
                             :: "r"(off), "r"(h01), "r"(h23) : "memory");
                asm volatile("st.shared.v2.b32 [%0], {%1, %2};"
                             :: "r"(off + A_HL), "r"(l01), "r"(l23) : "memory");
            }
            BAR_ARRIVE(FULL(slot));

            if (t + 1 < NT) {
#pragma unroll
                for (int ps = 0; ps < 4; ++ps) avc[ps] = avn[ps];
            }
        }

        // row sums: 8 lanes per row, reduce within each 8-lane group
#pragma unroll
        for (int ps = 0; ps < 4; ++ps) {
            float s = psum[ps];
            s += __shfl_xor_sync(0xffffffffu, s, 4);
            s += __shfl_xor_sync(0xffffffffu, s, 2);
            s += __shfl_xor_sync(0xffffffffu, s, 1);
            if ((lane & 7) == 0)
                ls[pw * 16 + ps * 4 + rsub] = s;
        }
    } else {
        // ================= CONSUMER =================
        const int cw = w - 8;            // 0..7
        const int mw = cw >> 1;          // 0..3 -> m base mw*32
        const int nw = cw & 1;           // 0..1 -> n base nw*32
        const int quad = lane >> 3, lr = lane & 7;
        const uint32_t aoff = (uint32_t)(((quad & 1) * 8 + lr) * APITCH
                                         + (quad >> 1) * 16);
        const uint32_t boff = (uint32_t)(((quad >> 1) * 8 + lr) * BPITCH
                                         + (quad & 1) * 16);
        const uint32_t aA0 = sbase + (mw * 32) * APITCH + aoff;
        const uint32_t aB0 = sbase + SB + (nw * 32) * BPITCH + boff;

        float acc[2][4][4];
#pragma unroll
        for (int i = 0; i < 2; ++i)
#pragma unroll
            for (int j = 0; j < 4; ++j)
#pragma unroll
                for (int k = 0; k < 4; ++k) acc[i][j][k] = 0.f;

#pragma unroll 1
        for (int t = 0; t < NT; ++t) {
            const int slot = t & 1;
            const int s = t >> 1;
            BAR_SYNC(FULL(slot));
            const uint32_t aAh = aA0 + slot * A_BUF;
            const uint32_t aAl = aAh + A_HL;
            const uint32_t aBh = aB0 + (s % 3) * B_BUF;
            const uint32_t aBl = aBh + B_HL;
            const uint32_t kb  = (t & 1) * 64;
#pragma unroll
            for (int kt = 0; kt < 2; ++kt) {
                const uint32_t koA = kt * 32;
                const uint32_t koB = kb + kt * 32;
                uint32_t ah0[4], ah1[4], bh0[4], bh1[4], bl0[4], bl1[4];
                uint32_t al0[4], al1[4];
                ldsm4(ah0, aAh + koA);
                ldsm4(ah1, aAh + 16 * APITCH + koA);
                ldsm4(bh0, aBh + koB);
                ldsm4(bh1, aBh + 16 * BPITCH + koB);
                // hh
                mma_bf16(acc[0][0], ah0, bh0[0], bh0[1]);
                mma_bf16(acc[0][1], ah0, bh0[2], bh0[3]);
                mma_bf16(acc[0][2], ah0, bh1[0], bh1[1]);
                mma_bf16(acc[0][3], ah0, bh1[2], bh1[3]);
                mma_bf16(acc[1][0], ah1, bh0[0], bh0[1]);
                mma_bf16(acc[1][1], ah1, bh0[2], bh0[3]);
                mma_bf16(acc[1][2], ah1, bh1[0], bh1[1]);
                mma_bf16(acc[1][3], ah1, bh1[2], bh1[3]);
                // hl
                ldsm4(bl0, aBl + koB);
                ldsm4(bl1, aBl + 16 * BPITCH + koB);
                mma_bf16(acc[0][0], ah0, bl0[0], bl0[1]);
                mma_bf16(acc[0][1], ah0, bl0[2], bl0[3]);
                mma_bf16(acc[0][2], ah0, bl1[0], bl1[1]);
                mma_bf16(acc[0][3], ah0, bl1[2], bl1[3]);
                mma_bf16(acc[1][0], ah1, bl0[0], bl0[1]);
                mma_bf16(acc[1][1], ah1, bl0[2], bl0[3]);
                mma_bf16(acc[1][2], ah1, bl1[0], bl1[1]);
                mma_bf16(acc[1][3], ah1, bl1[2], bl1[3]);
                // lh (ah dead -> al reuses its registers)
                ldsm4(al0, aAl + koA);
                ldsm4(al1, aAl + 16 * APITCH + koA);
                mma_bf16(acc[0][0], al0, bh0[0], bh0[1]);
                mma_bf16(acc[0][1], al0, bh0[2], bh0[3]);
                mma_bf16(acc[0][2], al0, bh1[0], bh1[1]);
                mma_bf16(acc[0][3], al0, bh1[2], bh1[3]);
                mma_bf16(acc[1][0], al1, bh0[0], bh0[1]);
                mma_bf16(acc[1][1], al1, bh0[2], bh0[3]);
                mma_bf16(acc[1][2], al1, bh1[0], bh1[1]);
                mma_bf16(acc[1][3], al1, bh1[2], bh1[3]);
            }
            BAR_ARRIVE(EMPTY(slot));
        }

        // epilogue deferred past the rejoin barrier (needs ls)
        __syncthreads();
        const size_t obase = (brow + i0) * F_OUT;
#pragma unroll
        for (int i = 0; i < 2; ++i) {
            const int r0 = mw * 32 + i * 16 + (lane >> 2);
            const float inv0 = 1.0f / ls[r0];
            const float inv1 = 1.0f / ls[r0 + 8];
#pragma unroll
            for (int j = 0; j < 4; ++j) {
                const int col = nw * 32 + j * 8 + 2 * (lane & 3);
                float x0 = acc[i][j][0] * inv0;
                float x1 = acc[i][j][1] * inv0;
                float x2 = acc[i][j][2] * inv1;
                float x3 = acc[i][j][3] * inv1;
                x0 = (x0 > 0.f) ? x0 : (expf(x0) - 1.f);
                x1 = (x1 > 0.f) ? x1 : (expf(x1) - 1.f);
                x2 = (x2 > 0.f) ? x2 : (expf(x2) - 1.f);
                x3 = (x3 > 0.f) ? x3 : (expf(x3) - 1.f);
                *(float2*)(out + obase + (size_t)r0 * F_OUT + col) =
                    make_float2(x0, x1);
                *(float2*)(out + obase + (size_t)(r0 + 8) * F_OUT + col) =
                    make_float2(x2, x3);
            }
        }
        return;
    }
    // producers rejoin the same barrier the consumers hit before their epilogue
    __syncthreads();
}

// ---------------------------------------------------------------------------
extern "C" void kernel_launch(void* const* d_in, const int* in_sizes, int n_in,
                              void* d_out, int out_size) {
    const float* h   = (const float*)d_in[0];
    const int*   adj = (const int*)d_in[1];
    const float* W   = (const float*)d_in[2];
    const float* a   = (const float*)d_in[3];
    float* out = (float*)d_out;
    (void)in_sizes; (void)n_in; (void)out_size;

    cudaFuncSetAttribute(k_wh, cudaFuncAttributeMaxDynamicSharedMemorySize,
                         WH_SMEM);
    cudaFuncSetAttribute(k_gat, cudaFuncAttributeMaxDynamicSharedMemorySize,
                         SMEM_TOTAL);

    k_wh<<<(B_DIM * M_DIM) / 64, 512, WH_SMEM>>>(h, W, a);

    dim3 grid2(M_DIM / BI, B_DIM);
    k_gat<<<grid2, 512, SMEM_TOTAL>>>(adj, out);
}